// round 16
// baseline (speedup 1.0000x reference)
#include <cuda_runtime.h>
#include <cuda_fp16.h>
#include <cstdint>

#define B_  2
#define S_  2048
#define D_  768
#define H_  12
#define HD_ 64
#define FF_ 3072
#define ROWS (B_ * S_)   // 4096

// ---------------- scratch (device globals; no allocation allowed) ----------
__device__ float  gQ  [ROWS * D_];
__device__ float  gK  [ROWS * D_];
__device__ float  gV  [ROWS * D_];
__device__ float  gTmp[ROWS * D_];
__device__ float  gX1 [ROWS * D_];
// fp16 operand buffers
__device__ __half gXh  [ROWS * D_];
__device__ __half gX1h [ROWS * D_];
__device__ __half gCtxh[ROWS * D_];
__device__ __half gFFh [ROWS * FF_];
__device__ __half gWQh [D_ * D_];
__device__ __half gWKh [D_ * D_];
__device__ __half gWVh [D_ * D_];
__device__ __half gWOh [D_ * D_];
__device__ __half gW1h [FF_ * D_];
__device__ __half gW2h [D_ * FF_];

// ---------------------------------------------------------------------------
// helpers
// ---------------------------------------------------------------------------
__device__ __forceinline__ uint32_t f2tf32(float x) {
    uint32_t u;
    asm("cvt.rna.tf32.f32 %0, %1;" : "=r"(u) : "f"(x));
    return u;
}

__device__ __forceinline__ void mma_tf32(float* c, const uint32_t* a, const uint32_t* b) {
    asm volatile(
        "mma.sync.aligned.m16n8k8.row.col.f32.tf32.tf32.f32 "
        "{%0,%1,%2,%3}, {%4,%5,%6,%7}, {%8,%9}, {%0,%1,%2,%3};"
        : "+f"(c[0]), "+f"(c[1]), "+f"(c[2]), "+f"(c[3])
        : "r"(a[0]), "r"(a[1]), "r"(a[2]), "r"(a[3]), "r"(b[0]), "r"(b[1]));
}

__device__ __forceinline__ void mma_f16(float* c, const uint32_t* a, const uint32_t* b) {
    asm volatile(
        "mma.sync.aligned.m16n8k16.row.col.f32.f16.f16.f32 "
        "{%0,%1,%2,%3}, {%4,%5,%6,%7}, {%8,%9}, {%0,%1,%2,%3};"
        : "+f"(c[0]), "+f"(c[1]), "+f"(c[2]), "+f"(c[3])
        : "r"(a[0]), "r"(a[1]), "r"(a[2]), "r"(a[3]), "r"(b[0]), "r"(b[1]));
}

__device__ __forceinline__ uint32_t smem_u32(const void* p) {
    uint32_t a;
    asm("{ .reg .u64 t; cvta.to.shared.u64 t, %1; cvt.u32.u64 %0, t; }"
        : "=r"(a) : "l"(p));
    return a;
}

__device__ __forceinline__ void cp_async16(uint32_t dst, const void* src) {
    asm volatile("cp.async.cg.shared.global [%0], [%1], 16;"
                 :: "r"(dst), "l"(src) : "memory");
}
__device__ __forceinline__ void cp_commit() {
    asm volatile("cp.async.commit_group;" ::: "memory");
}
template <int N>
__device__ __forceinline__ void cp_wait() {
    asm volatile("cp.async.wait_group %0;" :: "n"(N) : "memory");
}

// ---------------------------------------------------------------------------
// fp32 -> fp16 convert (memory-bound, ~1-3us each)
// ---------------------------------------------------------------------------
__global__ void __launch_bounds__(256)
f2h_kernel(const float* __restrict__ src, __half* __restrict__ dst, int n)
{
    const int i = (blockIdx.x * 256 + threadIdx.x) * 4;
    if (i < n) {
        float4 v = *(const float4*)(src + i);
        *(__half2*)(dst + i)     = __floats2half2_rn(v.x, v.y);
        *(__half2*)(dst + i + 2) = __floats2half2_rn(v.z, v.w);
    }
}

// ---------------------------------------------------------------------------
// fp16 mma.sync GEMM (NT), v5: C[m,n] = sum_k A[m,k]*B[n,k] + bias[n]
// Block 128x128, 128 threads = 4 warps (2M x 2N), warp tile 64x64.
// m16n8k16 f16 mma, fp32 accum. BK=32 halves (64B/row), 3-stage cp.async.
// Swizzle: 16B chunk c stored at c ^ ((row>>1)&3). Fragment LDS.32 bank =
// 16(gr&1) + 4((2ks+b)^((gr>>1)&3)) + qq : bijective onto 0..31 =>
// conflict-free; cp.async store phases likewise (derived in notes).
// Per-stage: A 8KB + B 8KB = 16KB; 3 stages = 48KB.
// ---------------------------------------------------------------------------
#define GEMM_SMEM_BYTES (3 * 16384)

template <int RELU, int OUTH>
__device__ __forceinline__ void
gemm_v5_body(const __half* __restrict__ A, const __half* __restrict__ Bm,
             const float* __restrict__ bias, float* __restrict__ C,
             __half* __restrict__ Ch,
             int N, int K, int bm, int bn, char* smem)
{
    const uint32_t sbase = smem_u32(smem);
    const int tid  = threadIdx.x;
    const int lane = tid & 31;
    const int warp = tid >> 5;
    const int wm = warp >> 1;
    const int wn = warp & 1;
    const int gr = lane >> 2;           // 0..7
    const int qq = lane & 3;            // 0..3
    const int nk = K >> 5;              // chunks of 32 halves

    // loader: thread t owns row t (all 4 chunks of A and B)
    const int lr = tid;
    const uint32_t rowoff = (uint32_t)lr * 64;
    const uint32_t rsw = (uint32_t)((lr >> 1) & 3);

    auto issue_loads = [&](int st, int k0) {
        const uint32_t dA = sbase + st * 16384;
        const uint32_t dB = dA + 8192;
        const __half* ga = A  + (size_t)(bm + lr) * K + k0;
        const __half* gb = Bm + (size_t)(bn + lr) * K + k0;
#pragma unroll
        for (int cch = 0; cch < 4; ++cch) {
            const uint32_t off = rowoff + ((cch ^ rsw) << 4);
            cp_async16(dA + off, ga + cch * 8);
            cp_async16(dB + off, gb + cch * 8);
        }
        cp_commit();
    };

    float acc[4][8][4];
#pragma unroll
    for (int mi = 0; mi < 4; ++mi)
#pragma unroll
        for (int ni = 0; ni < 8; ++ni)
#pragma unroll
            for (int r = 0; r < 4; ++r) acc[mi][ni][r] = 0.f;

    issue_loads(0, 0);
    if (nk > 1) issue_loads(1, 32);

    const uint32_t x3 = (uint32_t)((gr >> 1) & 3);

    for (int c = 0; c < nk; ++c) {
        if (c + 1 < nk) cp_wait<1>(); else cp_wait<0>();
        __syncthreads();

        if (c + 2 < nk) issue_loads((c + 2) % 3, (c + 2) * 32);

        const char* Ab = smem + (c % 3) * 16384;
        const char* Bb = Ab + 8192;

#pragma unroll
        for (int ks = 0; ks < 2; ++ks) {
            const uint32_t pc0 = (((uint32_t)(2 * ks)     ^ x3) << 4) + 4 * qq;
            const uint32_t pc1 = (((uint32_t)(2 * ks + 1) ^ x3) << 4) + 4 * qq;

            uint32_t a[4][4], b[8][2];
#pragma unroll
            for (int mi = 0; mi < 4; ++mi) {
                const uint32_t r0 = (uint32_t)(wm * 64 + mi * 16 + gr) * 64;
                a[mi][0] = *(const uint32_t*)(Ab + r0 + pc0);
                a[mi][1] = *(const uint32_t*)(Ab + r0 + 512 + pc0);
                a[mi][2] = *(const uint32_t*)(Ab + r0 + pc1);
                a[mi][3] = *(const uint32_t*)(Ab + r0 + 512 + pc1);
            }
#pragma unroll
            for (int ni = 0; ni < 8; ++ni) {
                const uint32_t nr = (uint32_t)(wn * 64 + ni * 8 + gr) * 64;
                b[ni][0] = *(const uint32_t*)(Bb + nr + pc0);
                b[ni][1] = *(const uint32_t*)(Bb + nr + pc1);
            }
#pragma unroll
            for (int mi = 0; mi < 4; ++mi)
#pragma unroll
                for (int ni = 0; ni < 8; ++ni)
                    mma_f16(acc[mi][ni], a[mi], b[ni]);
        }
    }

    // epilogue: c0:(gr,gc) c1:(gr,gc+1) c2:(gr+8,gc) c3:(gr+8,gc+1)
#pragma unroll
    for (int ni = 0; ni < 8; ++ni) {
        const int n0 = bn + wn * 64 + ni * 8 + qq * 2;
        const float2 bv = *(const float2*)&bias[n0];
#pragma unroll
        for (int mi = 0; mi < 4; ++mi) {
            const int row = bm + wm * 64 + mi * 16 + gr;
            float2 v0 = make_float2(acc[mi][ni][0] + bv.x, acc[mi][ni][1] + bv.y);
            float2 v1 = make_float2(acc[mi][ni][2] + bv.x, acc[mi][ni][3] + bv.y);
            if (RELU) {
                v0.x = fmaxf(v0.x, 0.f); v0.y = fmaxf(v0.y, 0.f);
                v1.x = fmaxf(v1.x, 0.f); v1.y = fmaxf(v1.y, 0.f);
            }
            if (OUTH) {
                *(__half2*)&Ch[(size_t)row * N + n0] =
                    __floats2half2_rn(v0.x, v0.y);
                *(__half2*)&Ch[(size_t)(row + 8) * N + n0] =
                    __floats2half2_rn(v1.x, v1.y);
            } else {
                *(float2*)&C[(size_t)row * N + n0]       = v0;
                *(float2*)&C[(size_t)(row + 8) * N + n0] = v1;
            }
        }
    }
}

template <int RELU>
__global__ void __launch_bounds__(128, 2)
gemm_v5_f(const __half* __restrict__ A, const __half* __restrict__ Bm,
          const float* __restrict__ bias, float* __restrict__ C, int N, int K)
{
    extern __shared__ char smem[];
    gemm_v5_body<RELU, 0>(A, Bm, bias, C, nullptr, N, K,
                          blockIdx.y * 128, blockIdx.x * 128, smem);
}

template <int RELU>
__global__ void __launch_bounds__(128, 2)
gemm_v5_h(const __half* __restrict__ A, const __half* __restrict__ Bm,
          const float* __restrict__ bias, __half* __restrict__ Ch, int N, int K)
{
    extern __shared__ char smem[];
    gemm_v5_body<RELU, 1>(A, Bm, bias, nullptr, Ch, N, K,
                          blockIdx.y * 128, blockIdx.x * 128, smem);
}

// fused QKV (fp16 in, fp32 out): blockIdx.z selects weight/bias/output
__global__ void __launch_bounds__(128, 2)
gemm_v5_qkv(const __half* __restrict__ xh,
            const __half* __restrict__ wqh, const float* __restrict__ bq,
            const __half* __restrict__ wkh, const float* __restrict__ bk,
            const __half* __restrict__ wvh, const float* __restrict__ bv,
            float* __restrict__ q, float* __restrict__ k, float* __restrict__ v)
{
    extern __shared__ char smem[];
    const __half* W; const float* bb; float* out;
    if (blockIdx.z == 0)      { W = wqh; bb = bq; out = q; }
    else if (blockIdx.z == 1) { W = wkh; bb = bk; out = k; }
    else                      { W = wvh; bb = bv; out = v; }
    gemm_v5_body<0, 0>(xh, W, bb, out, nullptr, D_, D_,
                       blockIdx.y * 128, blockIdx.x * 128, smem);
}

// ---------------------------------------------------------------------------
// Tensor-core flash attention (tf32 m16n8k8, fp32 softmax) — R7 proven;
// only change: context output written as fp16 for the projection GEMM.
// ---------------------------------------------------------------------------
#define ATTN_SMEM_BYTES (3 * 64 * 68 * 4)

__global__ void __launch_bounds__(128)
attn_tc_kernel(const float* __restrict__ Q, const float* __restrict__ K,
               const float* __restrict__ V, const float* __restrict__ alibi,
               __half* __restrict__ O)
{
    extern __shared__ uint32_t smem_u[];
    uint32_t (*Qs)[68] = (uint32_t (*)[68])(smem_u);
    uint32_t (*Ks)[68] = (uint32_t (*)[68])(smem_u + 64 * 68);
    uint32_t (*Vs)[68] = (uint32_t (*)[68])(smem_u + 2 * 64 * 68);

    const int bh = blockIdx.y;
    const int b  = bh / H_;
    const int h  = bh % H_;
    const int q0 = blockIdx.x * 64;
    const float slope = alibi[(size_t)h * S_ * S_ + 1];

    const int tid  = threadIdx.x;
    const int lane = tid & 31;
    const int warp = tid >> 5;
    const int gr = lane >> 2;
    const int qq = lane & 3;

    const float* qbase = Q + (size_t)(b * S_ + q0) * D_ + h * HD_;
    for (int i = tid; i < 64 * 16; i += 128) {
        int r = i >> 4, c = (i & 15) * 4;
        float4 v4 = *(const float4*)(qbase + (size_t)r * D_ + c);
        Qs[r][c + 0] = f2tf32(v4.x * 0.125f);
        Qs[r][c + 1] = f2tf32(v4.y * 0.125f);
        Qs[r][c + 2] = f2tf32(v4.z * 0.125f);
        Qs[r][c + 3] = f2tf32(v4.w * 0.125f);
    }
    __syncthreads();

    uint32_t qf[8][4];
    const int qr = warp * 16 + gr;
#pragma unroll
    for (int ks = 0; ks < 8; ++ks) {
        qf[ks][0] = Qs[qr][ks * 8 + qq];
        qf[ks][1] = Qs[qr + 8][ks * 8 + qq];
        qf[ks][2] = Qs[qr][ks * 8 + qq + 4];
        qf[ks][3] = Qs[qr + 8][ks * 8 + qq + 4];
    }

    float m0 = -1e30f, m1 = -1e30f, l0 = 0.f, l1 = 0.f;
    float oacc[8][4];
#pragma unroll
    for (int di = 0; di < 8; ++di)
#pragma unroll
        for (int r = 0; r < 4; ++r) oacc[di][r] = 0.f;

    const int gi0 = q0 + warp * 16 + gr;
    const int gi1 = gi0 + 8;

    const int ktiles = q0 / 64 + 1;
    for (int kt = 0; kt < ktiles; ++kt) {
        const int k0 = kt * 64;
        __syncthreads();
        const float* kbase = K + (size_t)(b * S_ + k0) * D_ + h * HD_;
        const float* vbase = V + (size_t)(b * S_ + k0) * D_ + h * HD_;
        for (int i = tid; i < 64 * 16; i += 128) {
            int r = i >> 4, c = (i & 15) * 4;
            float4 kv = *(const float4*)(kbase + (size_t)r * D_ + c);
            float4 vv = *(const float4*)(vbase + (size_t)r * D_ + c);
            Ks[r][c + 0] = f2tf32(kv.x); Ks[r][c + 1] = f2tf32(kv.y);
            Ks[r][c + 2] = f2tf32(kv.z); Ks[r][c + 3] = f2tf32(kv.w);
            Vs[r][c + 0] = f2tf32(vv.x); Vs[r][c + 1] = f2tf32(vv.y);
            Vs[r][c + 2] = f2tf32(vv.z); Vs[r][c + 3] = f2tf32(vv.w);
        }
        __syncthreads();

        float sc[8][4];
#pragma unroll
        for (int ni = 0; ni < 8; ++ni) {
            sc[ni][0] = 0.f; sc[ni][1] = 0.f; sc[ni][2] = 0.f; sc[ni][3] = 0.f;
#pragma unroll
            for (int ks = 0; ks < 8; ++ks) {
                uint32_t bf[2];
                bf[0] = Ks[ni * 8 + gr][ks * 8 + qq];
                bf[1] = Ks[ni * 8 + gr][ks * 8 + qq + 4];
                mma_tf32(sc[ni], qf[ks], bf);
            }
        }

        float rmax0 = -1e30f, rmax1 = -1e30f;
#pragma unroll
        for (int ni = 0; ni < 8; ++ni) {
            const int gj0 = k0 + ni * 8 + qq * 2;
            const int gj1 = gj0 + 1;
            sc[ni][0] = (gj0 <= gi0) ? sc[ni][0] + slope * (float)(gj0 - gi0) : -1e30f;
            sc[ni][1] = (gj1 <= gi0) ? sc[ni][1] + slope * (float)(gj1 - gi0) : -1e30f;
            sc[ni][2] = (gj0 <= gi1) ? sc[ni][2] + slope * (float)(gj0 - gi1) : -1e30f;
            sc[ni][3] = (gj1 <= gi1) ? sc[ni][3] + slope * (float)(gj1 - gi1) : -1e30f;
            rmax0 = fmaxf(rmax0, fmaxf(sc[ni][0], sc[ni][1]));
            rmax1 = fmaxf(rmax1, fmaxf(sc[ni][2], sc[ni][3]));
        }
        rmax0 = fmaxf(rmax0, __shfl_xor_sync(0xffffffffu, rmax0, 1));
        rmax0 = fmaxf(rmax0, __shfl_xor_sync(0xffffffffu, rmax0, 2));
        rmax1 = fmaxf(rmax1, __shfl_xor_sync(0xffffffffu, rmax1, 1));
        rmax1 = fmaxf(rmax1, __shfl_xor_sync(0xffffffffu, rmax1, 2));

        const float mn0 = fmaxf(m0, rmax0);
        const float mn1 = fmaxf(m1, rmax1);
        const float corr0 = __expf(m0 - mn0);
        const float corr1 = __expf(m1 - mn1);

        float rs0 = 0.f, rs1 = 0.f;
        uint32_t pf[8][4];
#pragma unroll
        for (int ni = 0; ni < 8; ++ni) {
            float p0 = __expf(sc[ni][0] - mn0);
            float p1 = __expf(sc[ni][1] - mn0);
            float p2 = __expf(sc[ni][2] - mn1);
            float p3 = __expf(sc[ni][3] - mn1);
            rs0 += p0 + p1;
            rs1 += p2 + p3;
            pf[ni][0] = f2tf32(p0);
            pf[ni][1] = f2tf32(p2);
            pf[ni][2] = f2tf32(p1);
            pf[ni][3] = f2tf32(p3);
        }
        rs0 += __shfl_xor_sync(0xffffffffu, rs0, 1);
        rs0 += __shfl_xor_sync(0xffffffffu, rs0, 2);
        rs1 += __shfl_xor_sync(0xffffffffu, rs1, 1);
        rs1 += __shfl_xor_sync(0xffffffffu, rs1, 2);

        l0 = l0 * corr0 + rs0;
        l1 = l1 * corr1 + rs1;
        m0 = mn0; m1 = mn1;

#pragma unroll
        for (int di = 0; di < 8; ++di) {
            oacc[di][0] *= corr0; oacc[di][1] *= corr0;
            oacc[di][2] *= corr1; oacc[di][3] *= corr1;
        }

#pragma unroll
        for (int di = 0; di < 8; ++di) {
#pragma unroll
            for (int ks = 0; ks < 8; ++ks) {
                uint32_t bf[2];
                bf[0] = Vs[ks * 8 + qq * 2][di * 8 + gr];
                bf[1] = Vs[ks * 8 + qq * 2 + 1][di * 8 + gr];
                mma_tf32(oacc[di], pf[ks], bf);
            }
        }
    }

    const float inv0 = 1.f / l0;
    const float inv1 = 1.f / l1;
    const size_t row0 = (size_t)(b * S_ + q0 + warp * 16 + gr);
#pragma unroll
    for (int di = 0; di < 8; ++di) {
        const int col = h * HD_ + di * 8 + qq * 2;
        *(__half2*)&O[row0 * D_ + col] =
            __floats2half2_rn(oacc[di][0] * inv0, oacc[di][1] * inv0);
        *(__half2*)&O[(row0 + 8) * D_ + col] =
            __floats2half2_rn(oacc[di][2] * inv1, oacc[di][3] * inv1);
    }
}

// ---------------------------------------------------------------------------
// out = LayerNorm(A_row + B_row) * g + beta ; optional fp16 copy of output.
// ---------------------------------------------------------------------------
template <int WH>
__global__ void __launch_bounds__(256)
add_ln_kernel(const float* __restrict__ A, const float* __restrict__ Bm,
              const float* __restrict__ g, const float* __restrict__ beta,
              float* __restrict__ out, __half* __restrict__ outh)
{
    const int row = blockIdx.x;
    const int tid = threadIdx.x;
    const float* a = A  + (size_t)row * D_;
    const float* b = Bm + (size_t)row * D_;

    float v[3], s = 0.f, ss = 0.f;
#pragma unroll
    for (int i = 0; i < 3; ++i) {
        int c = tid + i * 256;
        v[i] = a[c] + b[c];
        s  += v[i];
        ss += v[i] * v[i];
    }
#pragma unroll
    for (int o = 16; o > 0; o >>= 1) {
        s  += __shfl_xor_sync(0xffffffffu, s,  o);
        ss += __shfl_xor_sync(0xffffffffu, ss, o);
    }
    __shared__ float shs[8], shss[8];
    if ((tid & 31) == 0) { shs[tid >> 5] = s; shss[tid >> 5] = ss; }
    __syncthreads();
    __shared__ float sh_mean, sh_inv;
    if (tid == 0) {
        float ts = 0.f, tss = 0.f;
#pragma unroll
        for (int w = 0; w < 8; ++w) { ts += shs[w]; tss += shss[w]; }
        float mean = ts * (1.f / D_);
        float var  = tss * (1.f / D_) - mean * mean;
        sh_mean = mean;
        sh_inv  = rsqrtf(var + 1e-5f);
    }
    __syncthreads();
    const float mean = sh_mean, inv = sh_inv;
    float* o = out + (size_t)row * D_;
#pragma unroll
    for (int i = 0; i < 3; ++i) {
        int c = tid + i * 256;
        float val = (v[i] - mean) * inv * g[c] + beta[c];
        o[c] = val;
        if (WH) outh[(size_t)row * D_ + c] = __float2half_rn(val);
    }
}

// ---------------------------------------------------------------------------
static void* sym_addr(const void* symbol) {
    void* p = nullptr;
    cudaGetSymbolAddress(&p, symbol);
    return p;
}

extern "C" void kernel_launch(void* const* d_in, const int* in_sizes, int n_in,
                              void* d_out, int out_size)
{
    const float* x     = (const float*)d_in[0];
    // d_in[1] = mask (unused: causal handled analytically)
    const float* alibi = (const float*)d_in[2];
    const float* wq = (const float*)d_in[3];
    const float* bq = (const float*)d_in[4];
    const float* wk = (const float*)d_in[5];
    const float* bk = (const float*)d_in[6];
    const float* wv = (const float*)d_in[7];
    const float* bv = (const float*)d_in[8];
    const float* wo = (const float*)d_in[9];
    const float* bo = (const float*)d_in[10];
    const float* w1 = (const float*)d_in[11];
    const float* b1 = (const float*)d_in[12];
    const float* w2 = (const float*)d_in[13];
    const float* b2 = (const float*)d_in[14];
    const float* g1 = (const float*)d_in[15];
    const float* be1= (const float*)d_in[16];
    const float* g2 = (const float*)d_in[17];
    const float* be2= (const float*)d_in[18];
    float* out = (float*)d_out;

    float*  q    = (float*)sym_addr(gQ);
    float*  k    = (float*)sym_addr(gK);
    float*  v    = (float*)sym_addr(gV);
    float*  tmp  = (float*)sym_addr(gTmp);
    float*  x1   = (float*)sym_addr(gX1);
    __half* xh   = (__half*)sym_addr(gXh);
    __half* x1h  = (__half*)sym_addr(gX1h);
    __half* ctxh = (__half*)sym_addr(gCtxh);
    __half* ffh  = (__half*)sym_addr(gFFh);
    __half* wqh  = (__half*)sym_addr(gWQh);
    __half* wkh  = (__half*)sym_addr(gWKh);
    __half* wvh  = (__half*)sym_addr(gWVh);
    __half* woh  = (__half*)sym_addr(gWOh);
    __half* w1h  = (__half*)sym_addr(gW1h);
    __half* w2h  = (__half*)sym_addr(gW2h);

    cudaFuncSetAttribute(attn_tc_kernel,
                         cudaFuncAttributeMaxDynamicSharedMemorySize,
                         ATTN_SMEM_BYTES);
    cudaFuncSetAttribute(gemm_v5_qkv,
                         cudaFuncAttributeMaxDynamicSharedMemorySize,
                         GEMM_SMEM_BYTES);
    cudaFuncSetAttribute(gemm_v5_f<0>,
                         cudaFuncAttributeMaxDynamicSharedMemorySize,
                         GEMM_SMEM_BYTES);
    cudaFuncSetAttribute(gemm_v5_h<1>,
                         cudaFuncAttributeMaxDynamicSharedMemorySize,
                         GEMM_SMEM_BYTES);

    // fp32 -> fp16 operand conversion (memory-bound)
    const int DD = D_ * D_, FD = FF_ * D_, XN = ROWS * D_;
    f2h_kernel<<<(XN / 4 + 255) / 256, 256>>>(x,  xh,  XN);
    f2h_kernel<<<(DD / 4 + 255) / 256, 256>>>(wq, wqh, DD);
    f2h_kernel<<<(DD / 4 + 255) / 256, 256>>>(wk, wkh, DD);
    f2h_kernel<<<(DD / 4 + 255) / 256, 256>>>(wv, wvh, DD);
    f2h_kernel<<<(DD / 4 + 255) / 256, 256>>>(wo, woh, DD);
    f2h_kernel<<<(FD / 4 + 255) / 256, 256>>>(w1, w1h, FD);
    f2h_kernel<<<(FD / 4 + 255) / 256, 256>>>(w2, w2h, FD);

    // QKV projections fused into one launch (grid.z = 3), fp16 operands
    dim3 gqkv(D_ / 128, ROWS / 128, 3);
    gemm_v5_qkv<<<gqkv, 128, GEMM_SMEM_BYTES>>>(xh, wqh, bq, wkh, bk, wvh, bv,
                                                q, k, v);

    // attention (tf32 tensor cores, fp32 softmax), writes fp16 context
    dim3 gattn(S_ / 64, B_ * H_);
    attn_tc_kernel<<<gattn, 128, ATTN_SMEM_BYTES>>>(q, k, v, alibi, ctxh);

    // output projection (fp16 in, fp32 out), residual + LN1 (dual write)
    dim3 gproj(D_ / 128, ROWS / 128);
    gemm_v5_f<0><<<gproj, 128, GEMM_SMEM_BYTES>>>(ctxh, woh, bo, tmp, D_, D_);
    add_ln_kernel<1><<<ROWS, 256>>>(x, tmp, g1, be1, x1, x1h);

    // FFN: ffn1 writes fp16 directly (with ReLU), ffn2 back to fp32
    dim3 gff1(FF_ / 128, ROWS / 128);
    gemm_v5_h<1><<<gff1, 128, GEMM_SMEM_BYTES>>>(x1h, w1h, b1, ffh, FF_, D_);
    gemm_v5_f<0><<<gproj, 128, GEMM_SMEM_BYTES>>>(ffh, w2h, b2, tmp, D_, FF_);

    // residual + LN2 -> output
    add_ln_kernel<0><<<ROWS, 256>>>(x1, tmp, g2, be2, out, nullptr);
}